// round 3
// baseline (speedup 1.0000x reference)
#include <cuda_runtime.h>
#include <math.h>

#define B_ 4
#define I_ 512
#define K_ 512
#define C_ 64
#define EPS_LN 1e-5f

// -------- scratch (device globals; allocation is forbidden) --------
__device__ float   g_R [B_ * K_ * C_];      // (Q@W1^T+b1) / D
__device__ float   g_Va[B_ * I_ * C_];      // contraction result (pre-LN1)
__device__ float   g_Vp[B_ * I_ * C_];      // V + LN1(Va)@W2^T + b2 (pre-LN2)
__device__ double2 g_part1[B_ * I_];        // per-(b,i) {sum,sumsq} of Va
__device__ double2 g_part2[(B_ * I_) / 4];  // per-linear2-block {sum,sumsq} of Vp
__device__ float   g_mean1[B_], g_rstd1[B_];
__device__ float   g_mean2[B_], g_rstd2[B_];
__device__ unsigned g_cnt1;                 // zero-init; reset by last block
__device__ unsigned g_cnt2;

// ---------------------------------------------------------------
// Deterministic active-index compaction (ballot + popc prefix, fixed
// order). 512 mask entries, 8 warps x 2 groups of 32.
//   mstride : element stride between consecutive mask entries
//   offmul  : bytes per index unit (z row stride)
//   WMODE 0 : weight = m + 1e-6            [pass1]
//   WMODE 1 : weight = m * (m + 1e-6)      [pass2]
// s_iw[pos] = { weight, __int_as_float(byte_offset) }
// ---------------------------------------------------------------
template<int WMODE>
__device__ __forceinline__ int compact_active(const float* __restrict__ mp,
                                              size_t mstride, int offmul,
                                              float2* s_iw,
                                              int* s_cnt, int* s_off) {
    int t = threadIdx.x;
    int lane = t & 31, wid = t >> 5;
    float mv[2]; unsigned bal[2];
#pragma unroll
    for (int q = 0; q < 2; q++) {
        int g = wid + q * 8;
        int i = g * 32 + lane;
        mv[q] = __ldg(&mp[(size_t)i * mstride]);
        bal[q] = __ballot_sync(0xffffffffu, mv[q] != 0.f);
        if (lane == 0) s_cnt[g] = __popc(bal[q]);
    }
    __syncthreads();
    if (t == 0) {
        int acc = 0;
#pragma unroll
        for (int g = 0; g < 16; g++) { s_off[g] = acc; acc += s_cnt[g]; }
        s_off[16] = acc;
    }
    __syncthreads();
#pragma unroll
    for (int q = 0; q < 2; q++) {
        int g = wid + q * 8;
        int i = g * 32 + lane;
        if (mv[q] != 0.f) {
            int pos = s_off[g] + __popc(bal[q] & ((1u << lane) - 1u));
            float w = (WMODE == 0) ? (mv[q] + 1e-6f)
                                   : (mv[q] * (mv[q] + 1e-6f));
            s_iw[pos] = make_float2(w, __int_as_float(i * offmul));
        }
    }
    __syncthreads();
    return s_off[16];
}

// ---------------------------------------------------------------
// Pass 1 (+ fused linear1): per (b,k):
//   D[c]     = sum_{active i} exp(z[b,i,k,c]) * (m+1e-6)
//   Qa[c]    = b1[c] + sum_j Q[b,k,j] * W1[c,j]
//   R[b,k,c] = Qa[c] / D[c]
// 256 thr = 16 row-lanes x 16 float4-channel groups.
// ---------------------------------------------------------------
__global__ void k_pass1(const float* __restrict__ z,
                        const float* __restrict__ zm,
                        const float* __restrict__ Q,
                        const float* __restrict__ W1,
                        const float* __restrict__ b1) {
    int k = blockIdx.x, b = blockIdx.y;
    int t = threadIdx.x;
    __shared__ float2 s_iw[I_];
    __shared__ int    s_cnt[16];
    __shared__ int    s_off[17];
    __shared__ float4 red[16][16];
    __shared__ float  Qs[C_];
    __shared__ float  sD[C_];

    if (t < C_) Qs[t] = __ldg(&Q[((size_t)b * K_ + k) * C_ + t]);

    const float* mp = zm + (size_t)b * I_ * K_ + k;
    int nact = compact_active<0>(mp, K_, K_ * C_ * 4, s_iw, s_cnt, s_off);

    int c4 = t & 15;
    int di = t >> 4;
    const char* zb = (const char*)z
        + ((size_t)b * I_ * K_ + (size_t)k) * (C_ * 4) + c4 * 16;

    float4 acc = make_float4(0.f, 0.f, 0.f, 0.f);
#pragma unroll 8
    for (int j = di; j < nact; j += 16) {
        float2 iw = s_iw[j];
        float4 zv = *(const float4*)(zb + __float_as_int(iw.y));
        acc.x += __expf(zv.x) * iw.x;
        acc.y += __expf(zv.y) * iw.x;
        acc.z += __expf(zv.z) * iw.x;
        acc.w += __expf(zv.w) * iw.x;
    }
    red[di][c4] = acc;
    __syncthreads();
    if (t < 16) {
        float4 D = red[0][t];
#pragma unroll
        for (int r = 1; r < 16; r++) {
            float4 v = red[r][t];
            D.x += v.x; D.y += v.y; D.z += v.z; D.w += v.w;
        }
        ((float4*)sD)[t] = D;
    }
    __syncthreads();
    if (t < C_) {
        float acc2 = __ldg(&b1[t]);
        const float4* wrow = (const float4*)(W1 + t * C_);
        const float4* q4 = (const float4*)Qs;
#pragma unroll
        for (int j = 0; j < C_ / 4; j++) {
            float4 wv = __ldg(&wrow[j]);
            float4 qv = q4[j];
            acc2 += wv.x * qv.x + wv.y * qv.y + wv.z * qv.z + wv.w * qv.w;
        }
        g_R[((size_t)b * K_ + k) * C_ + t] = acc2 / sD[t];
    }
}

// ---------------------------------------------------------------
// Pass 2 (+ fused LN1 stats): per (b,i):
//   Va[b,i,c] = sum_{active k} m*(m+1e-6) * exp(z[b,i,k,c]) * R[b,k,c]
// Emits per-row {sum,sumsq}; LAST block reduces all partials to
// per-batch mean1/rstd1 (fixed order -> deterministic).
// ---------------------------------------------------------------
__global__ void k_pass2(const float* __restrict__ z,
                        const float* __restrict__ zm) {
    int i = blockIdx.x, b = blockIdx.y;
    int t = threadIdx.x;
    __shared__ float2 s_iw[K_];
    __shared__ int    s_cnt[16];
    __shared__ int    s_off[17];
    __shared__ float4 red[16][16];
    __shared__ double sd[16], sd2[16];
    __shared__ bool   isLast;

    const float* mp = zm + ((size_t)b * I_ + i) * K_;
    int nact = compact_active<1>(mp, 1, C_ * 4, s_iw, s_cnt, s_off);

    int c4 = t & 15;
    int dk = t >> 4;
    const char* zb = (const char*)z
        + ((size_t)b * I_ + i) * (size_t)(K_ * C_ * 4) + c4 * 16;
    const char* Rb = (const char*)g_R + (size_t)b * (K_ * C_ * 4) + c4 * 16;

    float4 acc = make_float4(0.f, 0.f, 0.f, 0.f);
#pragma unroll 4
    for (int j = dk; j < nact; j += 16) {
        float2 iw = s_iw[j];
        int off = __float_as_int(iw.y);
        float4 zv = *(const float4*)(zb + off);
        float4 Rv = *(const float4*)(Rb + off);
        acc.x += iw.x * __expf(zv.x) * Rv.x;
        acc.y += iw.x * __expf(zv.y) * Rv.y;
        acc.z += iw.x * __expf(zv.z) * Rv.z;
        acc.w += iw.x * __expf(zv.w) * Rv.w;
    }
    red[dk][c4] = acc;
    __syncthreads();
    if (t < 16) {
        float4 v = red[0][t];
#pragma unroll
        for (int r = 1; r < 16; r++) {
            float4 u = red[r][t];
            v.x += u.x; v.y += u.y; v.z += u.z; v.w += u.w;
        }
        ((float4*)g_Va)[((size_t)b * I_ + i) * (C_ / 4) + t] = v;
        sd [t] = (double)v.x + (double)v.y + (double)v.z + (double)v.w;
        sd2[t] = (double)v.x * v.x + (double)v.y * v.y
               + (double)v.z * v.z + (double)v.w * v.w;
    }
    __syncthreads();
    if (t == 0) {
        double s = 0.0, s2 = 0.0;
#pragma unroll
        for (int r = 0; r < 16; r++) { s += sd[r]; s2 += sd2[r]; }
        g_part1[(size_t)b * I_ + i] = make_double2(s, s2);
        __threadfence();
        unsigned v = atomicAdd(&g_cnt1, 1u);
        isLast = (v == (unsigned)(I_ * B_ - 1));
    }
    __syncthreads();
    if (isLast) {
        int wid = t >> 5, lane = t & 31;
        if (wid < B_) {
            double s = 0.0, s2 = 0.0;
            for (int j = lane; j < I_; j += 32) {
                double2 p = g_part1[(size_t)wid * I_ + j];
                s += p.x; s2 += p.y;
            }
#pragma unroll
            for (int o = 16; o > 0; o >>= 1) {
                s  += __shfl_down_sync(0xffffffffu, s,  o);
                s2 += __shfl_down_sync(0xffffffffu, s2, o);
            }
            if (lane == 0) {
                const double N = (double)(I_ * C_);
                double mu  = s / N;
                double var = s2 / N - mu * mu;
                g_mean1[wid] = (float)mu;
                g_rstd1[wid] = (float)(1.0 / sqrt(var + (double)EPS_LN));
            }
        }
        if (t == 0) g_cnt1 = 0;   // reset for next graph replay
    }
}

// ---------------------------------------------------------------
// Linear2 (+ fused LN2 stats): Vp = V + LN1(Va)@W2^T + b2.
// Per-block {sum,sumsq}; LAST block -> per-batch mean2/rstd2.
// ---------------------------------------------------------------
__global__ void k_linear2(const float* __restrict__ V,
                          const float* __restrict__ W2,
                          const float* __restrict__ b2) {
    __shared__ float  Ws[C_][C_ + 1];
    __shared__ float  Xs[4][C_];
    __shared__ double sh0[256], sh1[256];
    __shared__ bool   isLast;
    int t = threadIdx.x;
    for (int idx = t; idx < C_ * C_; idx += 256)
        Ws[idx / C_][idx % C_] = W2[idx];
    int r = t >> 6, c = t & 63;
    int grow = blockIdx.x * 4 + r;
    int b = grow >> 9;
    float mu = g_mean1[b], rs = g_rstd1[b];
    Xs[r][c] = (g_Va[(size_t)grow * C_ + c] - mu) * rs;
    __syncthreads();
    float acc = b2[c];
#pragma unroll
    for (int j = 0; j < C_; j++)
        acc += Xs[r][j] * Ws[c][j];
    float v = V[(size_t)grow * C_ + c] + acc;
    g_Vp[(size_t)grow * C_ + c] = v;

    sh0[t] = (double)v;
    sh1[t] = (double)v * (double)v;
    __syncthreads();
    for (int o = 128; o > 0; o >>= 1) {
        if (t < o) { sh0[t] += sh0[t + o]; sh1[t] += sh1[t + o]; }
        __syncthreads();
    }
    if (t == 0) {
        g_part2[blockIdx.x] = make_double2(sh0[0], sh1[0]);
        __threadfence();
        unsigned x = atomicAdd(&g_cnt2, 1u);
        isLast = (x == (unsigned)((B_ * I_) / 4 - 1));
    }
    __syncthreads();
    if (isLast) {
        int wid = t >> 5, lane = t & 31;
        const int PB = I_ / 4;                 // partials per batch = 128
        if (wid < B_) {
            double s = 0.0, s2 = 0.0;
            for (int j = lane; j < PB; j += 32) {
                double2 p = g_part2[(size_t)wid * PB + j];
                s += p.x; s2 += p.y;
            }
#pragma unroll
            for (int o = 16; o > 0; o >>= 1) {
                s  += __shfl_down_sync(0xffffffffu, s,  o);
                s2 += __shfl_down_sync(0xffffffffu, s2, o);
            }
            if (lane == 0) {
                const double N = (double)(I_ * C_);
                double mu  = s / N;
                double var = s2 / N - mu * mu;
                g_mean2[wid] = (float)mu;
                g_rstd2[wid] = (float)(1.0 / sqrt(var + (double)EPS_LN));
            }
        }
        if (t == 0) g_cnt2 = 0;
    }
}

// ---------------------------------------------------------------
// Final: out = (Vp - mean2[b]) * rstd2[b]
// ---------------------------------------------------------------
__global__ void k_final(float* __restrict__ out) {
    int idx = blockIdx.x * blockDim.x + threadIdx.x;
    int b = idx >> 15;
    out[idx] = (g_Vp[idx] - g_mean2[b]) * g_rstd2[b];
}

// ---------------------------------------------------------------
extern "C" void kernel_launch(void* const* d_in, const int* in_sizes, int n_in,
                              void* d_out, int out_size) {
    const float* V  = (const float*)d_in[0];
    const float* Q  = (const float*)d_in[1];
    const float* z  = (const float*)d_in[2];
    const float* zm = (const float*)d_in[3];
    const float* W1 = (const float*)d_in[4];
    const float* b1 = (const float*)d_in[5];
    const float* W2 = (const float*)d_in[6];
    const float* b2 = (const float*)d_in[7];
    float* out = (float*)d_out;

    k_pass1 <<<dim3(K_, B_), 256>>>(z, zm, Q, W1, b1);
    k_pass2 <<<dim3(I_, B_), 256>>>(z, zm);
    k_linear2<<<(B_ * I_) / 4, 256>>>(V, W2, b2);
    k_final <<<(B_ * I_ * C_) / 256, 256>>>(out);
}

// round 4
// speedup vs baseline: 1.2044x; 1.2044x over previous
#include <cuda_runtime.h>
#include <math.h>

#define B_ 4
#define I_ 512
#define K_ 512
#define C_ 64
#define EPS_LN 1e-5f

// -------- scratch (device globals; allocation is forbidden) --------
__device__ float   g_R [B_ * K_ * C_];      // (Q@W1^T+b1) / D
__device__ float   g_Va[B_ * I_ * C_];      // contraction result (pre-LN1)
__device__ float   g_Vp[B_ * I_ * C_];      // V + LN1(Va)@W2^T + b2 (pre-LN2)
__device__ double2 g_part1[B_ * I_];        // per-(b,i) {sum,sumsq} of Va
__device__ double2 g_part2[(B_ * I_) / 4];  // per-linear2-block {sum,sumsq}
__device__ float   g_mean1[B_], g_rstd1[B_];
__device__ float   g_mean2[B_], g_rstd2[B_];
__device__ unsigned g_cnt1;                 // zero-init; reset by last block
__device__ unsigned g_cnt2;

// ---------------------------------------------------------------
// Deterministic active-index compaction (ballot + popc prefix, fixed
// order). 512 mask entries, 8 warps x 2 groups of 32.  (R2-proven form)
//   WMODE 0 : weight = m + 1e-6            [pass1]
//   WMODE 1 : weight = m * (m + 1e-6)      [pass2]
// ---------------------------------------------------------------
template<int WMODE>
__device__ __forceinline__ int compact_active(const float* __restrict__ mp,
                                              size_t mstride,
                                              int* s_idx, float* s_w,
                                              int* s_cnt, int* s_off) {
    int t = threadIdx.x;
    int lane = t & 31, wid = t >> 5;
    float mv[2]; unsigned bal[2];
#pragma unroll
    for (int q = 0; q < 2; q++) {
        int g = wid + q * 8;
        int i = g * 32 + lane;
        mv[q] = __ldg(&mp[(size_t)i * mstride]);
        bal[q] = __ballot_sync(0xffffffffu, mv[q] != 0.f);
        if (lane == 0) s_cnt[g] = __popc(bal[q]);
    }
    __syncthreads();
    if (t == 0) {
        int acc = 0;
#pragma unroll
        for (int g = 0; g < 16; g++) { s_off[g] = acc; acc += s_cnt[g]; }
        s_off[16] = acc;
    }
    __syncthreads();
#pragma unroll
    for (int q = 0; q < 2; q++) {
        int g = wid + q * 8;
        int i = g * 32 + lane;
        if (mv[q] != 0.f) {
            int pos = s_off[g] + __popc(bal[q] & ((1u << lane) - 1u));
            s_idx[pos] = i;
            s_w[pos] = (WMODE == 0) ? (mv[q] + 1e-6f)
                                    : (mv[q] * (mv[q] + 1e-6f));
        }
    }
    __syncthreads();
    return s_off[16];
}

// ---------------------------------------------------------------
// Pass 1 (+ fused linear1): per (b,k):
//   D[c]     = sum_{active i} exp(z[b,i,k,c]) * (m+1e-6)
//   Qa[c]    = b1[c] + sum_j Q[b,k,j] * W1[c,j]   (smem-staged W1)
//   R[b,k,c] = Qa[c] / D[c]
// Main loop identical to R2's proven k_pass1 (unroll 4, index math).
// ---------------------------------------------------------------
__global__ void k_pass1(const float* __restrict__ z,
                        const float* __restrict__ zm,
                        const float* __restrict__ Q,
                        const float* __restrict__ W1,
                        const float* __restrict__ b1) {
    int k = blockIdx.x, b = blockIdx.y;
    int t = threadIdx.x;
    __shared__ int    s_idx[I_];
    __shared__ float  s_w[I_];
    __shared__ int    s_cnt[16];
    __shared__ int    s_off[17];
    __shared__ float4 red[16][16];
    __shared__ float  Ws[C_][C_ + 1];
    __shared__ float  Qs[C_];
    __shared__ float  sD[C_];

    // coalesced stage of W1 + this row of Q (completed by the
    // __syncthreads inside compact_active)
    for (int idx = t; idx < C_ * C_; idx += 256)
        Ws[idx / C_][idx % C_] = W1[idx];
    if (t < C_) Qs[t] = __ldg(&Q[((size_t)b * K_ + k) * C_ + t]);

    const float* mp = zm + (size_t)b * I_ * K_ + k;
    int nact = compact_active<0>(mp, K_, s_idx, s_w, s_cnt, s_off);

    int c4 = t & 15;        // float4 channel group
    int di = t >> 4;        // row lane
    const float4* zb = (const float4*)z
        + (((size_t)b * I_) * K_ + k) * (C_ / 4) + c4;
    const size_t zstride = (size_t)K_ * (C_ / 4);

    float4 acc = make_float4(0.f, 0.f, 0.f, 0.f);
#pragma unroll 4
    for (int j = di; j < nact; j += 16) {
        int i = s_idx[j];
        float w = s_w[j];
        float4 zv = __ldg(&zb[(size_t)i * zstride]);
        acc.x += __expf(zv.x) * w;
        acc.y += __expf(zv.y) * w;
        acc.z += __expf(zv.z) * w;
        acc.w += __expf(zv.w) * w;
    }
    red[di][c4] = acc;
    __syncthreads();
    if (t < 16) {
        float4 D = red[0][t];
#pragma unroll
        for (int r = 1; r < 16; r++) {
            float4 v = red[r][t];
            D.x += v.x; D.y += v.y; D.z += v.z; D.w += v.w;
        }
        ((float4*)sD)[t] = D;
    }
    __syncthreads();
    if (t < C_) {
        float acc2 = __ldg(&b1[t]);
#pragma unroll
        for (int j = 0; j < C_; j++)
            acc2 += Qs[j] * Ws[t][j];
        g_R[((size_t)b * K_ + k) * C_ + t] = acc2 / sD[t];
    }
}

// ---------------------------------------------------------------
// Pass 2 (+ fused LN1 stats): per (b,i):
//   Va[b,i,c] = sum_{active k} m*(m+1e-6) * exp(z[b,i,k,c]) * R[b,k,c]
// Main loop identical to R2's proven k_pass2. Last block reduces the
// per-row partials to per-batch mean1/rstd1 (fixed order).
// ---------------------------------------------------------------
__global__ void k_pass2(const float* __restrict__ z,
                        const float* __restrict__ zm) {
    int i = blockIdx.x, b = blockIdx.y;
    int t = threadIdx.x;
    __shared__ int    s_idx[K_];
    __shared__ float  s_w[K_];
    __shared__ int    s_cnt[16];
    __shared__ int    s_off[17];
    __shared__ float4 red[16][16];
    __shared__ double sd[16], sd2[16];
    __shared__ bool   isLast;

    const float* mp = zm + ((size_t)b * I_ + i) * K_;
    int nact = compact_active<1>(mp, 1, s_idx, s_w, s_cnt, s_off);

    int c4 = t & 15;
    int dk = t >> 4;
    const float4* zb = (const float4*)z
        + (((size_t)b * I_ + i) * K_) * (C_ / 4) + c4;
    const float4* Rb = (const float4*)g_R + ((size_t)b * K_) * (C_ / 4) + c4;

    float4 acc = make_float4(0.f, 0.f, 0.f, 0.f);
#pragma unroll 4
    for (int j = dk; j < nact; j += 16) {
        int kk = s_idx[j];
        float w = s_w[j];
        float4 zv = __ldg(&zb[(size_t)kk * (C_ / 4)]);
        float4 Rv = __ldg(&Rb[(size_t)kk * (C_ / 4)]);
        acc.x += w * __expf(zv.x) * Rv.x;
        acc.y += w * __expf(zv.y) * Rv.y;
        acc.z += w * __expf(zv.z) * Rv.z;
        acc.w += w * __expf(zv.w) * Rv.w;
    }
    red[dk][c4] = acc;
    __syncthreads();
    if (t < 16) {
        float4 v = red[0][t];
#pragma unroll
        for (int r = 1; r < 16; r++) {
            float4 u = red[r][t];
            v.x += u.x; v.y += u.y; v.z += u.z; v.w += u.w;
        }
        ((float4*)g_Va)[((size_t)b * I_ + i) * (C_ / 4) + t] = v;
        sd [t] = (double)v.x + (double)v.y + (double)v.z + (double)v.w;
        sd2[t] = (double)v.x * v.x + (double)v.y * v.y
               + (double)v.z * v.z + (double)v.w * v.w;
    }
    __syncthreads();
    if (t == 0) {
        double s = 0.0, s2 = 0.0;
#pragma unroll
        for (int r = 0; r < 16; r++) { s += sd[r]; s2 += sd2[r]; }
        g_part1[(size_t)b * I_ + i] = make_double2(s, s2);
        __threadfence();
        unsigned v = atomicAdd(&g_cnt1, 1u);
        isLast = (v == (unsigned)(I_ * B_ - 1));
    }
    __syncthreads();
    if (isLast) {
        int wid = t >> 5, lane = t & 31;
        if (wid < B_) {
            double s = 0.0, s2 = 0.0;
            for (int j = lane; j < I_; j += 32) {
                double2 p = g_part1[(size_t)wid * I_ + j];
                s += p.x; s2 += p.y;
            }
#pragma unroll
            for (int o = 16; o > 0; o >>= 1) {
                s  += __shfl_down_sync(0xffffffffu, s,  o);
                s2 += __shfl_down_sync(0xffffffffu, s2, o);
            }
            if (lane == 0) {
                const double N = (double)(I_ * C_);
                double mu  = s / N;
                double var = s2 / N - mu * mu;
                g_mean1[wid] = (float)mu;
                g_rstd1[wid] = (float)(1.0 / sqrt(var + (double)EPS_LN));
            }
        }
        if (t == 0) g_cnt1 = 0;   // reset for next graph replay
    }
}

// ---------------------------------------------------------------
// Linear2 (+ fused LN2 stats): Vp = V + LN1(Va)@W2^T + b2.
// ---------------------------------------------------------------
__global__ void k_linear2(const float* __restrict__ V,
                          const float* __restrict__ W2,
                          const float* __restrict__ b2) {
    __shared__ float  Ws[C_][C_ + 1];
    __shared__ float  Xs[4][C_];
    __shared__ double sh0[256], sh1[256];
    __shared__ bool   isLast;
    int t = threadIdx.x;
    for (int idx = t; idx < C_ * C_; idx += 256)
        Ws[idx / C_][idx % C_] = W2[idx];
    int r = t >> 6, c = t & 63;
    int grow = blockIdx.x * 4 + r;
    int b = grow >> 9;
    float mu = g_mean1[b], rs = g_rstd1[b];
    Xs[r][c] = (g_Va[(size_t)grow * C_ + c] - mu) * rs;
    __syncthreads();
    float acc = b2[c];
#pragma unroll
    for (int j = 0; j < C_; j++)
        acc += Xs[r][j] * Ws[c][j];
    float v = V[(size_t)grow * C_ + c] + acc;
    g_Vp[(size_t)grow * C_ + c] = v;

    sh0[t] = (double)v;
    sh1[t] = (double)v * (double)v;
    __syncthreads();
    for (int o = 128; o > 0; o >>= 1) {
        if (t < o) { sh0[t] += sh0[t + o]; sh1[t] += sh1[t + o]; }
        __syncthreads();
    }
    if (t == 0) {
        g_part2[blockIdx.x] = make_double2(sh0[0], sh1[0]);
        __threadfence();
        unsigned x = atomicAdd(&g_cnt2, 1u);
        isLast = (x == (unsigned)((B_ * I_) / 4 - 1));
    }
    __syncthreads();
    if (isLast) {
        int wid = t >> 5, lane = t & 31;
        const int PB = I_ / 4;                 // partials per batch = 128
        if (wid < B_) {
            double s = 0.0, s2 = 0.0;
            for (int j = lane; j < PB; j += 32) {
                double2 p = g_part2[(size_t)wid * PB + j];
                s += p.x; s2 += p.y;
            }
#pragma unroll
            for (int o = 16; o > 0; o >>= 1) {
                s  += __shfl_down_sync(0xffffffffu, s,  o);
                s2 += __shfl_down_sync(0xffffffffu, s2, o);
            }
            if (lane == 0) {
                const double N = (double)(I_ * C_);
                double mu  = s / N;
                double var = s2 / N - mu * mu;
                g_mean2[wid] = (float)mu;
                g_rstd2[wid] = (float)(1.0 / sqrt(var + (double)EPS_LN));
            }
        }
        if (t == 0) g_cnt2 = 0;
    }
}

// ---------------------------------------------------------------
// Final: out = (Vp - mean2[b]) * rstd2[b]
// ---------------------------------------------------------------
__global__ void k_final(float* __restrict__ out) {
    int idx = blockIdx.x * blockDim.x + threadIdx.x;
    int b = idx >> 15;
    out[idx] = (g_Vp[idx] - g_mean2[b]) * g_rstd2[b];
}

// ---------------------------------------------------------------
extern "C" void kernel_launch(void* const* d_in, const int* in_sizes, int n_in,
                              void* d_out, int out_size) {
    const float* V  = (const float*)d_in[0];
    const float* Q  = (const float*)d_in[1];
    const float* z  = (const float*)d_in[2];
    const float* zm = (const float*)d_in[3];
    const float* W1 = (const float*)d_in[4];
    const float* b1 = (const float*)d_in[5];
    const float* W2 = (const float*)d_in[6];
    const float* b2 = (const float*)d_in[7];
    float* out = (float*)d_out;

    k_pass1  <<<dim3(K_, B_), 256>>>(z, zm, Q, W1, b1);
    k_pass2  <<<dim3(I_, B_), 256>>>(z, zm);
    k_linear2<<<(B_ * I_) / 4, 256>>>(V, W2, b2);
    k_final  <<<(B_ * I_ * C_) / 256, 256>>>(out);
}